// round 11
// baseline (speedup 1.0000x reference)
#include <cuda_runtime.h>
#include <stdint.h>

#define N_ITERS 40
#define BATCH   128
#define T_TOK   32768
#define BLOCK_THREADS  512
#define ROWS_PER_TILE  64
#define ROWS_PER_WARP  4
#define TILES_X        (T_TOK / ROWS_PER_TILE)    // 512 tiles per iteration
#define TILES_TOTAL    (N_ITERS * TILES_X)        // 20480
#define GRID_BLOCKS    608                        // 152 SMs * 4 resident blocks

// Persistent single-wave kernel: 608 blocks, each walks a contiguous chunk of
// ~34 tiles (64 rows each). Eliminates the ~40 wave transitions of the
// launch-per-tile version; the segment scan amortizes to ~1-2 per block
// (chunk crosses an iteration boundary at most once). Copy inner loop is the
// proven MLP=4 shape (4 independent LDG.128 then 4 STG.128 per warp).
__global__ __launch_bounds__(BLOCK_THREADS) void seg_reverse_persistent_kernel(
    const void* __restrict__ sizes_raw,
    const float4* __restrict__ data, float4* __restrict__ out) {
    __shared__ int s_ends[BATCH];
    __shared__ int s_src[ROWS_PER_TILE];
    __shared__ int s_warp[4];

    const int tid  = threadIdx.x;
    const int lane = tid & 31;
    const int warp = tid >> 5;

    const int*       s32 = (const int*)sizes_raw;
    const long long* s64 = (const long long*)sizes_raw;

    const int chunk = (TILES_TOTAL + GRID_BLOCKS - 1) / GRID_BLOCKS;  // 34
    const int t_begin = blockIdx.x * chunk;
    const int t_end   = min(t_begin + chunk, TILES_TOTAL);

    int cur_n = -1;

    for (int tile = t_begin; tile < t_end; ++tile) {
        const int n = tile >> 9;          // tile / TILES_X
        const int x = tile & (TILES_X - 1);

        // Protect s_src (and s_ends on rescan) against the previous tile's
        // in-flight copy reads. Uniform control flow across the block.
        __syncthreads();

        if (n != cur_n) {
            cur_n = n;
            // ---- inclusive scan of 128 segment sizes (threads 0-127) ----
            int v = 0;
            if (tid < BATCH) v = s32[n * BATCH + tid];
            #pragma unroll
            for (int d = 1; d < 32; d <<= 1) {
                int u = __shfl_up_sync(0xffffffffu, v, d);
                if (lane >= d) v += u;
            }
            if (tid < BATCH && lane == 31) s_warp[warp] = v;
            __syncthreads();
            int total = s_warp[0] + s_warp[1] + s_warp[2] + s_warp[3];

            if (total != T_TOK) {
                // sizes stored as int64: rescan using low word of each 8B elem.
                __syncthreads();
                v = 0;
                if (tid < BATCH) v = (int)s64[(size_t)n * BATCH + tid];
                #pragma unroll
                for (int d = 1; d < 32; d <<= 1) {
                    int u = __shfl_up_sync(0xffffffffu, v, d);
                    if (lane >= d) v += u;
                }
                if (tid < BATCH && lane == 31) s_warp[warp] = v;
                __syncthreads();
            }

            if (tid < BATCH) {
                int add = 0;
                #pragma unroll
                for (int w = 0; w < 3; ++w) if (w < warp) add += s_warp[w];
                s_ends[tid] = v + add;
            }
            __syncthreads();
        }

        // ---- per-row source index: searchsorted(ends, t, 'right') ----
        const int row0 = x * ROWS_PER_TILE;
        if (tid < ROWS_PER_TILE) {
            const int t = row0 + tid;
            int lo = 0, hi = BATCH;
            #pragma unroll
            for (int s = 0; s < 8; ++s) {   // answer in [0,128] -> 8 steps
                int mid = (lo + hi) >> 1;
                if (s_ends[mid] > t) hi = mid; else lo = mid + 1;
            }
            const int seg   = (lo < BATCH) ? lo : (BATCH - 1);
            const int end   = s_ends[seg];
            const int start = seg ? s_ends[seg - 1] : 0;
            int src = start + end - 1 - t;
            src = src < 0 ? 0 : (src >= T_TOK ? T_TOK - 1 : src);
            s_src[tid] = src;
        }
        __syncthreads();

        // ---- copy: 4 independent 512B row reads in flight, 4 writes ----
        const size_t base = (size_t)n * T_TOK;
        const int r = warp * ROWS_PER_WARP;

        float4 v0 = __ldcs(&data[(base + (size_t)s_src[r + 0]) * 32 + lane]);
        float4 v1 = __ldcs(&data[(base + (size_t)s_src[r + 1]) * 32 + lane]);
        float4 v2 = __ldcs(&data[(base + (size_t)s_src[r + 2]) * 32 + lane]);
        float4 v3 = __ldcs(&data[(base + (size_t)s_src[r + 3]) * 32 + lane]);

        const size_t o = (base + (size_t)(row0 + r)) * 32 + lane;
        __stcs(&out[o +  0], v0);
        __stcs(&out[o + 32], v1);
        __stcs(&out[o + 64], v2);
        __stcs(&out[o + 96], v3);
    }
}

extern "C" void kernel_launch(void* const* d_in, const int* in_sizes, int n_in,
                              void* d_out, int out_size) {
    // Identify which input is `sizes` (N_ITERS*BATCH elements) vs `data`.
    const void*   sizes = d_in[0];
    const float4* data  = (const float4*)d_in[1];
    if (n_in >= 2 && in_sizes[0] != N_ITERS * BATCH) {
        sizes = d_in[1];
        data  = (const float4*)d_in[0];
    }
    float4* out = (float4*)d_out;

    seg_reverse_persistent_kernel<<<GRID_BLOCKS, BLOCK_THREADS>>>(sizes, data, out);
}

// round 12
// speedup vs baseline: 1.1279x; 1.1279x over previous
#include <cuda_runtime.h>
#include <stdint.h>

#define N_ITERS 40
#define BATCH   128
#define T_TOK   32768
#define BLOCK_THREADS  512
#define ROWS_PER_BLOCK 64
#define ROWS_PER_WARP  4

// Fused: each block recomputes its iteration's segment-end offsets inline
// (512B of sizes, L2-resident), then gathers 64 token rows.
// 512 threads/block. Threads 0-127 scan; threads 0-63 binary-search;
// each of the 16 warps moves 4 rows with 4 independent LDG.128 in flight.
//
// CONVERGED (final). Measured map of the design space on GB300:
//   - this shape: 188-189us kernel, 86% DRAM (6.8TB/s) — best
//   - MLP=8 per warp: regs 24->40, occ 63%, 191.8us (regressed)
//   - 128-row blocks: wave granularity, 193.8us (regressed)
//   - persistent 608-block single wave: per-tile __syncthreads drains
//     cross-tile MLP, DRAM 78%, 208.8us (regressed)
// The residual ~14% DRAM idle is read<->write turnaround on a 1:1
// bidirectional stream; bytes are irreducible (exact f32 permutation).
__global__ __launch_bounds__(BLOCK_THREADS) void seg_reverse_fused_kernel(
    const void* __restrict__ sizes_raw,
    const float4* __restrict__ data, float4* __restrict__ out) {
    __shared__ int s_ends[BATCH];
    __shared__ int s_src[ROWS_PER_BLOCK];
    __shared__ int s_warp[4];

    const int n    = blockIdx.y;
    const int tid  = threadIdx.x;
    const int lane = tid & 31;
    const int warp = tid >> 5;

    const int*       s32 = (const int*)sizes_raw;
    const long long* s64 = (const long long*)sizes_raw;

    // ---- inclusive scan of 128 segment sizes (threads 0-127) ----
    int v = 0;
    if (tid < BATCH) v = s32[n * BATCH + tid];
    #pragma unroll
    for (int d = 1; d < 32; d <<= 1) {
        int u = __shfl_up_sync(0xffffffffu, v, d);
        if (lane >= d) v += u;
    }
    if (tid < BATCH && lane == 31) s_warp[warp] = v;
    __syncthreads();
    int total = s_warp[0] + s_warp[1] + s_warp[2] + s_warp[3];

    if (total != T_TOK) {
        // sizes stored as int64: rescan using low word of each 8B element.
        __syncthreads();
        v = 0;
        if (tid < BATCH) v = (int)s64[(size_t)n * BATCH + tid];
        #pragma unroll
        for (int d = 1; d < 32; d <<= 1) {
            int u = __shfl_up_sync(0xffffffffu, v, d);
            if (lane >= d) v += u;
        }
        if (tid < BATCH && lane == 31) s_warp[warp] = v;
        __syncthreads();
    }

    if (tid < BATCH) {
        int add = 0;
        #pragma unroll
        for (int w = 0; w < 3; ++w) if (w < warp) add += s_warp[w];
        s_ends[tid] = v + add;
    }
    __syncthreads();

    // ---- per-row source index: searchsorted(ends, t, 'right') ----
    const int row0 = blockIdx.x * ROWS_PER_BLOCK;
    if (tid < ROWS_PER_BLOCK) {
        const int t = row0 + tid;
        int lo = 0, hi = BATCH;
        #pragma unroll
        for (int s = 0; s < 8; ++s) {   // answer in [0,128] -> 8 bisect steps
            int mid = (lo + hi) >> 1;
            if (s_ends[mid] > t) hi = mid; else lo = mid + 1;
        }
        const int seg   = (lo < BATCH) ? lo : (BATCH - 1);
        const int end   = s_ends[seg];
        const int start = seg ? s_ends[seg - 1] : 0;
        int src = start + end - 1 - t;
        src = src < 0 ? 0 : (src >= T_TOK ? T_TOK - 1 : src);
        s_src[tid] = src;
    }
    __syncthreads();

    // ---- copy: 4 independent 512B row reads in flight, then 4 writes ----
    const size_t base = (size_t)n * T_TOK;
    const int r = warp * ROWS_PER_WARP;

    float4 v0 = __ldcs(&data[(base + (size_t)s_src[r + 0]) * 32 + lane]);
    float4 v1 = __ldcs(&data[(base + (size_t)s_src[r + 1]) * 32 + lane]);
    float4 v2 = __ldcs(&data[(base + (size_t)s_src[r + 2]) * 32 + lane]);
    float4 v3 = __ldcs(&data[(base + (size_t)s_src[r + 3]) * 32 + lane]);

    const size_t o = (base + (size_t)(row0 + r)) * 32 + lane;
    __stcs(&out[o +  0], v0);
    __stcs(&out[o + 32], v1);
    __stcs(&out[o + 64], v2);
    __stcs(&out[o + 96], v3);
}

extern "C" void kernel_launch(void* const* d_in, const int* in_sizes, int n_in,
                              void* d_out, int out_size) {
    // Identify which input is `sizes` (N_ITERS*BATCH elements) vs `data`.
    const void*   sizes = d_in[0];
    const float4* data  = (const float4*)d_in[1];
    if (n_in >= 2 && in_sizes[0] != N_ITERS * BATCH) {
        sizes = d_in[1];
        data  = (const float4*)d_in[0];
    }
    float4* out = (float4*)d_out;

    dim3 grid(T_TOK / ROWS_PER_BLOCK, N_ITERS);
    seg_reverse_fused_kernel<<<grid, BLOCK_THREADS>>>(sizes, data, out);
}